// round 7
// baseline (speedup 1.0000x reference)
#include <cuda_runtime.h>
#include <cuda_fp16.h>
#include <math.h>
#include <cstdint>

// ---------------- problem constants ----------------------------------------
#define NB    8
#define Cc    256
#define HW    961
#define Mrows 7688
#define MP    7808          // padded M = 61*128
#define HID   512
#define OUTF  256

// ---------------- scratch (device globals; zero-initialized) ----------------
__device__ float  g_S0 [NB * Cc];
__device__ __half g_W1h[Cc * HID];      // planar [k][n]
__device__ __half g_W2h[HID * OUTF];    // planar [k][n]
__device__ float  g_H1T[HID * MP];
__device__ float  g_S1T[HID * 16];
__device__ float  g_H2T[OUTF * MP];

// ---------------- helpers ----------------------------------------------------
__device__ __forceinline__ uint32_t smem_u32(const void* p) {
    uint32_t a;
    asm("{ .reg .u64 t; cvta.to.shared.u64 t, %1; cvt.u32.u64 %0, t; }"
        : "=r"(a) : "l"(p));
    return a;
}

__device__ __forceinline__ float dinv_of(int b) {
    int deg = (b == 0 || b == NB - 1) ? 963 : 964;
    return 1.0f / sqrtf((float)deg);
}

#define MMA_F16(d, a, b) \
    asm volatile("mma.sync.aligned.m16n8k16.row.col.f32.f16.f16.f32 " \
                 "{%0,%1,%2,%3},{%4,%5,%6,%7},{%8,%9},{%0,%1,%2,%3};" \
                 : "+f"((d)[0]), "+f"((d)[1]), "+f"((d)[2]), "+f"((d)[3]) \
                 : "r"((a)[0]), "r"((a)[1]), "r"((a)[2]), "r"((a)[3]), \
                   "r"((b)[0]), "r"((b)[1]))

#define LDSM_X4_TRANS(r0, r1, r2, r3, addr) \
    asm volatile("ldmatrix.sync.aligned.m8n8.x4.trans.shared.b16 {%0,%1,%2,%3}, [%4];" \
                 : "=r"(r0), "=r"(r1), "=r"(r2), "=r"(r3) : "r"(addr))

#define CP_ASYNC16(dst32, src) \
    asm volatile("cp.async.cg.shared.global [%0], [%1], 16;" :: "r"(dst32), "l"(src))
#define CP_COMMIT()  asm volatile("cp.async.commit_group;" ::: "memory")
#define CP_WAIT1()   asm volatile("cp.async.wait_group 1;" ::: "memory")

// ---------------- small kernels ----------------------------------------------
__global__ void sum_x_kernel(const float* __restrict__ x, float* __restrict__ S0) {
    int bc = blockIdx.x;
    const float* src = x + (size_t)bc * HW;
    float s = 0.f;
    for (int p = threadIdx.x; p < HW; p += 256) s += src[p];
    __shared__ float red[8];
    #pragma unroll
    for (int off = 16; off; off >>= 1) s += __shfl_down_sync(0xffffffffu, s, off);
    if ((threadIdx.x & 31) == 0) red[threadIdx.x >> 5] = s;
    __syncthreads();
    if (threadIdx.x < 8) {
        s = red[threadIdx.x];
        #pragma unroll
        for (int off = 4; off; off >>= 1) s += __shfl_down_sync(0xffu, s, off);
        if (threadIdx.x == 0) S0[bc] = s;
    }
}

// W[Nr][Kc] row-major fp32 -> planar fp16 [Kc][Nr]
__global__ void wsplit_h(const float* __restrict__ W, __half* __restrict__ Wh,
                         int Nr, int Kc) {
    __shared__ float t[32][33];
    int n0 = blockIdx.x * 32, k0 = blockIdx.y * 32;
    int tx = threadIdx.x, ty = threadIdx.y;
    #pragma unroll
    for (int r = 0; r < 4; r++)
        t[ty + 8 * r][tx] = W[(size_t)(n0 + ty + 8 * r) * Kc + k0 + tx];
    __syncthreads();
    #pragma unroll
    for (int r = 0; r < 4; r++) {
        int k = ty + 8 * r;
        Wh[(size_t)(k0 + k) * Nr + n0 + tx] = __float2half_rn(t[tx][k]);
    }
}

// per-(feature, sample) sums of H1T rows -> S1T[k][16]
__global__ void sum_h(const float* __restrict__ H1T, float* __restrict__ S1T) {
    int k = blockIdx.x;
    int w = threadIdx.x >> 5, lane = threadIdx.x & 31;
    const float* src = H1T + (size_t)k * MP + w * HW;
    float s = 0.f;
    #pragma unroll 8
    for (int p = lane; p < HW; p += 32) s += src[p];
    #pragma unroll
    for (int off = 16; off; off >>= 1) s += __shfl_down_sync(0xffffffffu, s, off);
    if (lane == 0) S1T[k * 16 + w] = s;
}

// max over samples
__global__ void max_k(const float* __restrict__ H2T, float* __restrict__ out) {
    int idx = blockIdx.x * 256 + threadIdx.x;
    if (idx >= OUTF * HW) return;
    int o = idx / HW, p = idx - o * HW;
    const float* src = H2T + (size_t)o * MP + p;
    float m = -INFINITY;
    #pragma unroll
    for (int b = 0; b < NB; b++) m = fmaxf(m, src[b * HW]);
    out[idx] = m;
}

// ---------------- fp16 mma.sync GEMM, 64x128 CTA tile, ldmatrix --------------
// C^T[n][m] = lrelu( sum_k A[m][k]*W[n][k] + bias[n] )
// W planar fp16 [k][n] in gmem.  A built on the fly:
//   MODE 0: from x + S0 (input aggregation fused)
//   MODE 1: from H1T + S1T (hidden aggregation fused)
template<int KTOT, int NTOT, int MODE>
__global__ __launch_bounds__(256)
void gemm_f16(const float* __restrict__ SRC, const float* __restrict__ SUM,
              const __half* __restrict__ Bh,
              const float* __restrict__ bias, float* __restrict__ CT) {
    extern __shared__ __half smh[];
    constexpr int AROWH  = 72;               // halfs per k-row (64 + 8 pad)
    constexpr int BROWH  = 136;              // halfs per k-row (128 + 8 pad)
    constexpr int ATILEH = 32 * AROWH;       // 2304
    constexpr int BTILEH = 32 * BROWH;       // 4352
    constexpr int STAGEH = ATILEH + BTILEH;  // 6656 halfs
    constexpr int NC     = KTOT / 32;

    const int tid  = threadIdx.x;
    const int lane = tid & 31;
    const int wid  = tid >> 5;
    const int bm   = blockIdx.y * 64;
    const int bn   = blockIdx.x * 128;
    const int wm   = (wid & 1) * 32;
    const int wn   = (wid >> 1) * 32;
    const int g    = lane >> 2, tg = lane & 3;
    const uint32_t sb = smem_u32(smh);

    float acc[2][4][4];
    #pragma unroll
    for (int i = 0; i < 2; i++)
        #pragma unroll
        for (int j = 0; j < 4; j++)
            #pragma unroll
            for (int e = 0; e < 4; e++) acc[i][j][e] = 0.f;

    auto load_chunk = [&](int ch) {
        const int st = ch & 1;
        const int k0 = ch * 32;
        __half* As = smh + st * STAGEH;
        const uint32_t bB = sb + (uint32_t)(st * STAGEH + ATILEH) * 2;
        // ---- B tile via cp.async: 32 k-rows x 128 n halfs ----
        #pragma unroll
        for (int i = 0; i < 2; i++) {
            int q   = tid + i * 256;           // 0..511
            int row = q >> 4, c16 = q & 15;
            const __half* src = Bh + (size_t)(k0 + row) * NTOT + bn + c16 * 8;
            uint32_t dst = bB + (uint32_t)(row * BROWH + c16 * 8) * 2;
            CP_ASYNC16(dst, src);
        }
        // ---- A tile computed: 32 k-rows x 64 m, 2 m per thread ----
        #pragma unroll
        for (int i = 0; i < 4; i++) {
            int q   = tid + i * 256;           // 0..1023
            int k_l = q >> 5;                  // 0..31
            int mi  = (q & 31) * 2;
            int k   = k0 + k_l;
            int m   = bm + mi;
            float v[2];
            #pragma unroll
            for (int e = 0; e < 2; e++) {
                int mm = m + e;
                float vv;
                if (MODE == 0) {
                    if (mm < Mrows) {
                        int b = mm / HW, p = mm - b * HW;
                        float db = dinv_of(b);
                        size_t xi = (size_t)(b * Cc + k) * HW + p;
                        vv = db * db * (__ldg(&SUM[b * Cc + k]) + __ldg(&SRC[xi]));
                        if (b > 0)      vv += db * dinv_of(b - 1) * __ldg(&SRC[xi - (size_t)Cc * HW]);
                        if (b < NB - 1) vv += db * dinv_of(b + 1) * __ldg(&SRC[xi + (size_t)Cc * HW]);
                    } else vv = 0.f;
                } else {
                    int b = mm / HW; if (b > NB - 1) b = NB - 1;
                    float db = dinv_of(b);
                    const float* hp = SRC + (size_t)k * MP + mm;
                    vv = db * db * (__ldg(&SUM[k * 16 + b]) + __ldg(hp));
                    if (b > 0)      vv += db * dinv_of(b - 1) * __ldg(hp - HW);
                    if (b < NB - 1) vv += db * dinv_of(b + 1) * __ldg(hp + HW);
                }
                v[e] = vv;
            }
            *(__half2*)(As + k_l * AROWH + mi) = __floats2half2_rn(v[0], v[1]);
        }
    };

    // prologue
    load_chunk(0);
    CP_COMMIT();

    const int r   = lane & 7;
    const int sel = lane >> 3;

    for (int ch = 0; ch < NC; ch++) {
        if (ch + 1 < NC) load_chunk(ch + 1);
        CP_COMMIT();
        CP_WAIT1();
        __syncthreads();

        const int st = ch & 1;
        const uint32_t aBase = sb + (uint32_t)(st * STAGEH) * 2;
        const uint32_t bBase = sb + (uint32_t)(st * STAGEH + ATILEH) * 2;

        #pragma unroll
        for (int kk = 0; kk < 2; kk++) {
            const int kb = kk * 16;
            // A fragments: one ldmatrix.x4.trans per mt
            uint32_t a[2][4];
            #pragma unroll
            for (int mt = 0; mt < 2; mt++) {
                int mb = wm + mt * 16;
                int kof = kb + r + ((sel & 2) ? 8 : 0);
                int mof = mb + ((sel & 1) ? 8 : 0);
                uint32_t addr = aBase + (uint32_t)(kof * AROWH + mof) * 2;
                LDSM_X4_TRANS(a[mt][0], a[mt][1], a[mt][2], a[mt][3], addr);
            }
            // B fragments: one ldmatrix.x4.trans per pair of nt
            uint32_t bfr[4][2];
            #pragma unroll
            for (int np = 0; np < 2; np++) {
                int nb = wn + np * 16;
                int kof = kb + r + ((sel & 1) ? 8 : 0);
                int nof = nb + ((sel & 2) ? 8 : 0);
                uint32_t addr = bBase + (uint32_t)(kof * BROWH + nof) * 2;
                LDSM_X4_TRANS(bfr[2 * np][0], bfr[2 * np][1],
                              bfr[2 * np + 1][0], bfr[2 * np + 1][1], addr);
            }
            #pragma unroll
            for (int mt = 0; mt < 2; mt++)
                #pragma unroll
                for (int nt = 0; nt < 4; nt++)
                    MMA_F16(acc[mt][nt], a[mt], bfr[nt]);
        }
        __syncthreads();
    }

    // epilogue: bias + leaky relu, store transposed CT[n][m]
    #pragma unroll
    for (int mt = 0; mt < 2; mt++) {
        int m0 = bm + wm + mt * 16 + g;
        bool v0 = m0 < Mrows, v8 = (m0 + 8) < Mrows;
        #pragma unroll
        for (int nt = 0; nt < 4; nt++) {
            int n = bn + wn + nt * 8 + 2 * tg;
            float bb0 = __ldg(&bias[n]), bb1 = __ldg(&bias[n + 1]);
            float c0 = acc[mt][nt][0] + bb0;
            float c1 = acc[mt][nt][1] + bb1;
            float c2 = acc[mt][nt][2] + bb0;
            float c3 = acc[mt][nt][3] + bb1;
            c0 = c0 > 0.f ? c0 : 0.01f * c0;
            c1 = c1 > 0.f ? c1 : 0.01f * c1;
            c2 = c2 > 0.f ? c2 : 0.01f * c2;
            c3 = c3 > 0.f ? c3 : 0.01f * c3;
            if (v0) {
                CT[(size_t)n * MP + m0]       = c0;
                CT[(size_t)(n + 1) * MP + m0] = c1;
            }
            if (v8) {
                CT[(size_t)n * MP + m0 + 8]       = c2;
                CT[(size_t)(n + 1) * MP + m0 + 8] = c3;
            }
        }
    }
}

// ---------------- launcher ----------------------------------------------------
extern "C" void kernel_launch(void* const* d_in, const int* in_sizes, int n_in,
                              void* d_out, int out_size) {
    const float* x  = (const float*)d_in[0];
    const float* W1 = (const float*)d_in[1];
    const float* b1 = (const float*)d_in[2];
    const float* W2 = (const float*)d_in[3];
    const float* b2 = (const float*)d_in[4];
    float* out = (float*)d_out;

    float *S0, *H1T, *S1T, *H2T;
    __half *W1h, *W2h;
    cudaGetSymbolAddress((void**)&S0,  g_S0);
    cudaGetSymbolAddress((void**)&W1h, g_W1h);
    cudaGetSymbolAddress((void**)&W2h, g_W2h);
    cudaGetSymbolAddress((void**)&H1T, g_H1T);
    cudaGetSymbolAddress((void**)&S1T, g_S1T);
    cudaGetSymbolAddress((void**)&H2T, g_H2T);

    constexpr int SMEM = 2 * (32 * 72 + 32 * 136) * 2;   // 26624 B
    cudaFuncSetAttribute(gemm_f16<Cc,  HID,  0>,
                         cudaFuncAttributeMaxDynamicSharedMemorySize, SMEM);
    cudaFuncSetAttribute(gemm_f16<HID, OUTF, 1>,
                         cudaFuncAttributeMaxDynamicSharedMemorySize, SMEM);

    // 1) per-sample channel sums of x; weight transpose to planar fp16
    sum_x_kernel<<<NB * Cc, 256>>>(x, S0);
    wsplit_h<<<dim3(HID / 32, Cc / 32), dim3(32, 8)>>>(W1, W1h, HID, Cc);
    wsplit_h<<<dim3(OUTF / 32, HID / 32), dim3(32, 8)>>>(W2, W2h, OUTF, HID);

    // 2) GEMM1 (input aggregation fused): H1T = lrelu(agg(x) @ W1^T + b1)^T
    gemm_f16<Cc, HID, 0><<<dim3(HID / 128, MP / 64), 256, SMEM>>>(
        x, S0, W1h, b1, H1T);

    // 3) per-sample sums of H1
    sum_h<<<HID, 256>>>(H1T, S1T);

    // 4) GEMM2 (hidden aggregation fused): H2T = lrelu(agg(H1) @ W2^T + b2)^T
    gemm_f16<HID, OUTF, 1><<<dim3(OUTF / 128, MP / 64), 256, SMEM>>>(
        H1T, S1T, W2h, b2, H2T);

    // 5) max over samples
    max_k<<<(OUTF * HW + 255) / 256, 256>>>(H2T, out);
}

// round 8
// speedup vs baseline: 2.1485x; 2.1485x over previous
#include <cuda_runtime.h>
#include <cuda_fp16.h>
#include <math.h>
#include <cstdint>

// ---------------- problem constants ----------------------------------------
#define NB    8
#define Cc    256
#define HW    961
#define Mrows 7688
#define MP    7808          // padded M = 61*128
#define HID   512
#define OUTF  256

// ---------------- scratch (device globals; zero-initialized) ----------------
__device__ float    g_S0  [NB * Cc];
__device__ uint32_t g_YP  [(Cc / 2) * MP];     // packed fp16x2 (k even|odd)
__device__ uint32_t g_W1hP[(Cc / 2) * HID];    // weights fp16x2 packed [k/2][n]
__device__ uint32_t g_W2hP[(HID / 2) * OUTF];
__device__ float    g_H1T [HID * MP];
__device__ float    g_S1T [HID * 16];
__device__ float    g_H2T [OUTF * MP];

// ---------------- helpers ----------------------------------------------------
__device__ __forceinline__ uint32_t smem_u32(const void* p) {
    uint32_t a;
    asm("{ .reg .u64 t; cvta.to.shared.u64 t, %1; cvt.u32.u64 %0, t; }"
        : "=r"(a) : "l"(p));
    return a;
}

__device__ __forceinline__ float dinv_of(int b) {
    int deg = (b == 0 || b == NB - 1) ? 963 : 964;
    return 1.0f / sqrtf((float)deg);
}

__device__ __forceinline__ uint32_t f16x2_pack(float v0, float v1) {
    __half2 h = __floats2half2_rn(v0, v1);
    return *(uint32_t*)&h;
}

#define MMA_F16(d, a, b) \
    asm volatile("mma.sync.aligned.m16n8k16.row.col.f32.f16.f16.f32 " \
                 "{%0,%1,%2,%3},{%4,%5,%6,%7},{%8,%9},{%0,%1,%2,%3};" \
                 : "+f"((d)[0]), "+f"((d)[1]), "+f"((d)[2]), "+f"((d)[3]) \
                 : "r"((a)[0]), "r"((a)[1]), "r"((a)[2]), "r"((a)[3]), \
                   "r"((b)[0]), "r"((b)[1]))

#define CP_ASYNC16(dst32, src) \
    asm volatile("cp.async.cg.shared.global [%0], [%1], 16;" :: "r"(dst32), "l"(src))
#define CP_COMMIT()  asm volatile("cp.async.commit_group;" ::: "memory")
#define CP_WAIT1()   asm volatile("cp.async.wait_group 1;" ::: "memory")

// ---------------- small kernels ----------------------------------------------
__global__ void sum_x_kernel(const float* __restrict__ x, float* __restrict__ S0) {
    int bc = blockIdx.x;
    const float* src = x + (size_t)bc * HW;
    float s = 0.f;
    for (int p = threadIdx.x; p < HW; p += 256) s += src[p];
    __shared__ float red[8];
    #pragma unroll
    for (int off = 16; off; off >>= 1) s += __shfl_down_sync(0xffffffffu, s, off);
    if ((threadIdx.x & 31) == 0) red[threadIdx.x >> 5] = s;
    __syncthreads();
    if (threadIdx.x < 8) {
        s = red[threadIdx.x];
        #pragma unroll
        for (int off = 4; off; off >>= 1) s += __shfl_down_sync(0xffu, s, off);
        if (threadIdx.x == 0) S0[bc] = s;
    }
}

// W[Nr][Kc] row-major -> packed fp16x2 [Kc/2][Nr]
__global__ void wsplit_p(const float* __restrict__ W,
                         uint32_t* __restrict__ WhP, int Nr, int Kc) {
    __shared__ float t[32][33];
    int n0 = blockIdx.x * 32, k0 = blockIdx.y * 32;
    int tx = threadIdx.x, ty = threadIdx.y;
    #pragma unroll
    for (int r = 0; r < 4; r++)
        t[ty + 8 * r][tx] = W[(size_t)(n0 + ty + 8 * r) * Kc + k0 + tx];
    __syncthreads();
    #pragma unroll
    for (int r = 0; r < 2; r++) {
        int k2l = ty + 8 * r;                 // 0..15
        size_t o = (size_t)(k0 / 2 + k2l) * Nr + n0 + tx;
        WhP[o] = f16x2_pack(t[tx][2 * k2l], t[tx][2 * k2l + 1]);
    }
}

// aggregation on x -> packed fp16x2 [Cc/2][MP]
__global__ void agg_x_f16(const float* __restrict__ x, const float* __restrict__ S0,
                          uint32_t* __restrict__ YP) {
    int c2 = blockIdx.y;                      // 0..127
    int m  = blockIdx.x * 256 + threadIdx.x;
    if (m >= Mrows) return;
    int b = m / HW, p = m - b * HW;
    float db = dinv_of(b);
    float c0 = db * db;
    float cm = (b > 0)      ? db * dinv_of(b - 1) : 0.f;
    float cp = (b < NB - 1) ? db * dinv_of(b + 1) : 0.f;
    float v[2];
    #pragma unroll
    for (int e = 0; e < 2; e++) {
        int c = 2 * c2 + e;
        size_t xi = (size_t)(b * Cc + c) * HW + p;
        float vv = c0 * (S0[b * Cc + c] + x[xi]);
        if (b > 0)      vv += cm * x[xi - (size_t)Cc * HW];
        if (b < NB - 1) vv += cp * x[xi + (size_t)Cc * HW];
        v[e] = vv;
    }
    YP[(size_t)c2 * MP + m] = f16x2_pack(v[0], v[1]);
}

// per-(feature, sample) sums of H1T rows -> S1T[k][16]
__global__ void sum_h(const float* __restrict__ H1T, float* __restrict__ S1T) {
    int k = blockIdx.x;
    int w = threadIdx.x >> 5, lane = threadIdx.x & 31;
    const float* src = H1T + (size_t)k * MP + w * HW;
    float s = 0.f;
    #pragma unroll 8
    for (int p = lane; p < HW; p += 32) s += src[p];
    #pragma unroll
    for (int off = 16; off; off >>= 1) s += __shfl_down_sync(0xffffffffu, s, off);
    if (lane == 0) S1T[k * 16 + w] = s;
}

// max over samples
__global__ void max_k(const float* __restrict__ H2T, float* __restrict__ out) {
    int idx = blockIdx.x * 256 + threadIdx.x;
    if (idx >= OUTF * HW) return;
    int o = idx / HW, p = idx - o * HW;
    const float* src = H2T + (size_t)o * MP + p;
    float m = -INFINITY;
    #pragma unroll
    for (int b = 0; b < NB; b++) m = fmaxf(m, src[b * HW]);
    out[idx] = m;
}

// ---------------- fp16 single-product mma.sync GEMM, 64x128 CTA tile ---------
// C^T[n][m] = lrelu( sum_k A[m][k]*W[n][k] + bias[n] )
// A fp16x2 packed [k/2][m]; W fp16x2 packed [k/2][n].
// AGG: A built on the fly from H1T (fp32 k-major) + S1T per-sample sums.
template<int KTOT, int NTOT, bool AGG>
__global__ __launch_bounds__(256)
void gemm_mma(const uint32_t* __restrict__ AP,
              const float* __restrict__ H1T, const float* __restrict__ S1T,
              const uint32_t* __restrict__ BhP,
              const float* __restrict__ bias, float* __restrict__ CT) {
    extern __shared__ uint32_t smu[];
    constexpr int AROW  = 68;              // words per k2-row (64 + pad)
    constexpr int BROW  = 132;             // words per k2-row (128 + pad)
    constexpr int ATILE = 16 * AROW;       // 1088
    constexpr int BTILE = 16 * BROW;       // 2112
    constexpr int BUFW  = ATILE + BTILE;   // 3200 words
    constexpr int NC    = KTOT / 32;

    const int tid  = threadIdx.x;
    const int lane = tid & 31;
    const int wid  = tid >> 5;
    const int bm   = blockIdx.y * 64;
    const int bn   = blockIdx.x * 128;
    const int wm   = (wid & 1) * 32;
    const int wn   = (wid >> 1) * 32;
    const int g    = lane >> 2, tg = lane & 3;
    const uint32_t sb = smem_u32(smu);

    float acc[2][4][4];
    #pragma unroll
    for (int i = 0; i < 2; i++)
        #pragma unroll
        for (int j = 0; j < 4; j++)
            #pragma unroll
            for (int e = 0; e < 4; e++) acc[i][j][e] = 0.f;

    auto load_chunk = [&](int ch) {
        const int st   = ch & 1;
        const int k2_0 = ch * 16;
        const uint32_t bufb = sb + (uint32_t)(st * BUFW) * 4;
        // B tile via cp.async: 16 k2-rows x 128 words, 2 ops/thread
        #pragma unroll
        for (int i = 0; i < 2; i++) {
            int q   = tid + i * 256;       // 0..511
            int row = q >> 5, c = q & 31;
            const uint32_t* src = BhP + (size_t)(k2_0 + row) * NTOT + bn + c * 4;
            uint32_t dst = bufb + (uint32_t)(ATILE + row * BROW + c * 4) * 4;
            CP_ASYNC16(dst, src);
        }
        if (!AGG) {
            // A tile via cp.async: 16 rows x 64 words, 1 op/thread
            int row = tid >> 4, c = tid & 15;
            const uint32_t* src = AP + (size_t)(k2_0 + row) * MP + bm + c * 4;
            uint32_t dst = bufb + (uint32_t)(row * AROW + c * 4) * 4;
            CP_ASYNC16(dst, src);
        } else {
            // A computed: agg(H1) -> fp16x2
            uint32_t* bA = smu + st * BUFW;
            const int k0 = ch * 32;
            #pragma unroll
            for (int i = 0; i < 4; i++) {
                int q   = tid + i * 256;   // 0..1023
                int k2l = q >> 6;          // 0..15
                int mi  = q & 63;
                int k   = k0 + 2 * k2l;
                int m   = bm + mi;
                int b = m / HW; if (b > NB - 1) b = NB - 1;
                float db = dinv_of(b);
                float c0 = db * db;
                float cm = (b > 0)      ? db * dinv_of(b - 1) : 0.f;
                float cp = (b < NB - 1) ? db * dinv_of(b + 1) : 0.f;
                const float* h0 = H1T + (size_t)k * MP + m;
                const float* h1 = h0 + MP;
                float v0 = c0 * (__ldg(&S1T[k * 16 + b]) + __ldg(h0));
                float v1 = c0 * (__ldg(&S1T[(k + 1) * 16 + b]) + __ldg(h1));
                if (b > 0) {
                    v0 += cm * __ldg(h0 - HW);
                    v1 += cm * __ldg(h1 - HW);
                }
                if (b < NB - 1) {
                    v0 += cp * __ldg(h0 + HW);
                    v1 += cp * __ldg(h1 + HW);
                }
                bA[k2l * AROW + mi] = f16x2_pack(v0, v1);
            }
        }
    };

    // prologue
    load_chunk(0);
    CP_COMMIT();

    for (int ch = 0; ch < NC; ch++) {
        if (ch + 1 < NC) load_chunk(ch + 1);
        CP_COMMIT();
        CP_WAIT1();
        __syncthreads();

        const uint32_t* Ab = smu + (ch & 1) * BUFW;
        const uint32_t* Bh = Ab + ATILE;

        #pragma unroll
        for (int kk = 0; kk < 2; kk++) {
            const int kb = kk * 8;
            uint32_t a[2][4], bh[4][2];
            #pragma unroll
            for (int mt = 0; mt < 2; mt++) {
                int mb = wm + mt * 16 + g;
                a[mt][0] = Ab[(kb + tg) * AROW + mb];
                a[mt][1] = Ab[(kb + tg) * AROW + mb + 8];
                a[mt][2] = Ab[(kb + tg + 4) * AROW + mb];
                a[mt][3] = Ab[(kb + tg + 4) * AROW + mb + 8];
            }
            #pragma unroll
            for (int nt = 0; nt < 4; nt++) {
                int nb = wn + nt * 8 + g;
                bh[nt][0] = Bh[(kb + tg) * BROW + nb];
                bh[nt][1] = Bh[(kb + tg + 4) * BROW + nb];
            }
            #pragma unroll
            for (int mt = 0; mt < 2; mt++)
                #pragma unroll
                for (int nt = 0; nt < 4; nt++)
                    MMA_F16(acc[mt][nt], a[mt], bh[nt]);
        }
        __syncthreads();
    }

    // epilogue: bias + leaky relu, store transposed CT[n][m]
    #pragma unroll
    for (int mt = 0; mt < 2; mt++) {
        int m0 = bm + wm + mt * 16 + g;
        bool v0 = m0 < Mrows, v8 = (m0 + 8) < Mrows;
        #pragma unroll
        for (int nt = 0; nt < 4; nt++) {
            int n = bn + wn + nt * 8 + 2 * tg;
            float bb0 = __ldg(&bias[n]), bb1 = __ldg(&bias[n + 1]);
            float c0 = acc[mt][nt][0] + bb0;
            float c1 = acc[mt][nt][1] + bb1;
            float c2 = acc[mt][nt][2] + bb0;
            float c3 = acc[mt][nt][3] + bb1;
            c0 = c0 > 0.f ? c0 : 0.01f * c0;
            c1 = c1 > 0.f ? c1 : 0.01f * c1;
            c2 = c2 > 0.f ? c2 : 0.01f * c2;
            c3 = c3 > 0.f ? c3 : 0.01f * c3;
            if (v0) {
                CT[(size_t)n * MP + m0]       = c0;
                CT[(size_t)(n + 1) * MP + m0] = c1;
            }
            if (v8) {
                CT[(size_t)n * MP + m0 + 8]       = c2;
                CT[(size_t)(n + 1) * MP + m0 + 8] = c3;
            }
        }
    }
}

// ---------------- launcher ----------------------------------------------------
extern "C" void kernel_launch(void* const* d_in, const int* in_sizes, int n_in,
                              void* d_out, int out_size) {
    const float* x  = (const float*)d_in[0];
    const float* W1 = (const float*)d_in[1];
    const float* b1 = (const float*)d_in[2];
    const float* W2 = (const float*)d_in[3];
    const float* b2 = (const float*)d_in[4];
    float* out = (float*)d_out;

    float *S0, *H1T, *S1T, *H2T;
    uint32_t *YP, *W1h, *W2h;
    cudaGetSymbolAddress((void**)&S0,  g_S0);
    cudaGetSymbolAddress((void**)&YP,  g_YP);
    cudaGetSymbolAddress((void**)&W1h, g_W1hP);
    cudaGetSymbolAddress((void**)&W2h, g_W2hP);
    cudaGetSymbolAddress((void**)&H1T, g_H1T);
    cudaGetSymbolAddress((void**)&S1T, g_S1T);
    cudaGetSymbolAddress((void**)&H2T, g_H2T);

    constexpr int SMEM = 2 * 3200 * 4;   // 25600 B
    cudaFuncSetAttribute(gemm_mma<Cc,  HID,  false>,
                         cudaFuncAttributeMaxDynamicSharedMemorySize, SMEM);
    cudaFuncSetAttribute(gemm_mma<HID, OUTF, true>,
                         cudaFuncAttributeMaxDynamicSharedMemorySize, SMEM);

    // 1) per-sample channel sums of x; weight transpose to packed fp16x2
    sum_x_kernel<<<NB * Cc, 256>>>(x, S0);
    wsplit_p<<<dim3(HID / 32, Cc / 32), dim3(32, 8)>>>(W1, W1h, HID, Cc);
    wsplit_p<<<dim3(OUTF / 32, HID / 32), dim3(32, 8)>>>(W2, W2h, OUTF, HID);

    // 2) aggregation on x -> packed fp16 Y
    agg_x_f16<<<dim3((Mrows + 255) / 256, Cc / 2), 256>>>(x, S0, YP);

    // 3) GEMM1: H1T = lrelu(Y @ W1^T + b1)^T
    gemm_mma<Cc, HID, false><<<dim3(HID / 128, MP / 64), 256, SMEM>>>(
        YP, nullptr, nullptr, W1h, b1, H1T);

    // 4) per-sample sums of H1
    sum_h<<<HID, 256>>>(H1T, S1T);

    // 5) GEMM2 (fused aggregation): H2T = lrelu(agg(H1) @ W2^T + b2)^T
    gemm_mma<HID, OUTF, true><<<dim3(OUTF / 128, MP / 64), 256, SMEM>>>(
        nullptr, H1T, S1T, W2h, b2, H2T);

    // 6) max over samples
    max_k<<<(OUTF * HW + 255) / 256, 256>>>(H2T, out);
}